// round 10
// baseline (speedup 1.0000x reference)
#include <cuda_runtime.h>
#include <cuda_fp16.h>
#include <math.h>
#include <cstdint>

#define N_TOTAL 4096
#define HALF    2048
#define DIM     256
#define EPS     1e-6f
#define MARGIN  0.3f

#define BM   128
#define BN   128
#define KBLK 64                 // fp16 k-elements per block (128 B row)
#define NKB  (DIM / KBLK)       // 4 k-blocks
#define ROWB 144                // smem row stride bytes (128B data + 16B pad)
#define TILEB (BM * ROWB)       // 18432 B per tile buffer
#define NCTA (HALF / BM) * (HALF / BN)   // 256

// Scratch (allocation-free)
__device__ __half   g_h[N_TOTAL * DIM];
__device__ float    g_sq[N_TOTAL];
__device__ unsigned g_ap[N_TOTAL];   // d^2 max over positives (bits), init 0
__device__ unsigned g_an[N_TOTAL];   // d^2 min over negatives (bits), init +inf
__device__ unsigned g_done;          // completion ticket, reset by k_normalize

static __device__ __forceinline__ unsigned su32(const void* p) {
    return (unsigned)__cvta_generic_to_shared(p);
}

// ---------------------------------------------------------------------------
// Kernel 1: L2-normalize rows -> fp16 + fp32 squared norm; reinit buffers.
// One warp per row.
// ---------------------------------------------------------------------------
__global__ void k_normalize(const float* __restrict__ in) {
    int warp = (blockIdx.x * blockDim.x + threadIdx.x) >> 5;
    int lane = threadIdx.x & 31;
    if (warp >= N_TOTAL) return;

    const float4* row = (const float4*)(in + (size_t)warp * DIM);
    float4 v0 = row[lane];
    float4 v1 = row[lane + 32];
    float s = v0.x*v0.x + v0.y*v0.y + v0.z*v0.z + v0.w*v0.w
            + v1.x*v1.x + v1.y*v1.y + v1.z*v1.z + v1.w*v1.w;
    #pragma unroll
    for (int o = 16; o; o >>= 1) s += __shfl_xor_sync(0xffffffffu, s, o);

    float inv = 1.0f / (sqrtf(s) + EPS);

    __half2 h0 = __floats2half2_rn(v0.x * inv, v0.y * inv);
    __half2 h1 = __floats2half2_rn(v0.z * inv, v0.w * inv);
    __half2 h2 = __floats2half2_rn(v1.x * inv, v1.y * inv);
    __half2 h3 = __floats2half2_rn(v1.z * inv, v1.w * inv);

    __half* H = g_h + (size_t)warp * DIM;
    *(__half2*)(H + 4 * lane)           = h0;
    *(__half2*)(H + 4 * lane + 2)       = h1;
    *(__half2*)(H + 128 + 4 * lane)     = h2;
    *(__half2*)(H + 128 + 4 * lane + 2) = h3;

    if (lane == 0) {
        g_sq[warp] = s * inv * inv;
        g_ap[warp] = 0u;
        g_an[warp] = 0x7F800000u;
    }
    if (blockIdx.x == 0 && threadIdx.x == 0) g_done = 0u;
}

// ---------------------------------------------------------------------------
// Kernel 2: fp16 mma.sync 128x128 GEMM, cp.async double-buffered 64-wide
// k-blocks, fused SQUARED-distance hard mining, and (last CTA) final loss.
// 256 threads = 8 warps (2x4); warp tile 64x32.
// ---------------------------------------------------------------------------
__global__ void __launch_bounds__(256, 2) k_mine(const int* __restrict__ tgt,
                                                 float* __restrict__ out) {
    extern __shared__ __align__(128) char dyn[];   // [2][TILEB] A then [2][TILEB] B
    __shared__ unsigned s_rp[BM], s_rn[BM], s_cp[BN], s_cn[BN];
    __shared__ int   s_lr[BM], s_lc[BN];
    __shared__ float s_sqr[BM], s_sqc[BN];
    __shared__ float s_red[256];
    __shared__ unsigned s_ticket;

    const int tid  = threadIdx.x, lane = tid & 31, w = tid >> 5;
    const int row0 = blockIdx.y * BM;
    const int col0 = blockIdx.x * BN;

    if (tid < 128) {
        s_rp[tid] = 0u;          s_rn[tid] = 0x7F800000u;
        s_cp[tid] = 0u;          s_cn[tid] = 0x7F800000u;
        s_lr[tid]  = tgt[row0 + tid];
        s_lc[tid]  = tgt[HALF + col0 + tid];
        s_sqr[tid] = g_sq[row0 + tid];
        s_sqc[tid] = g_sq[HALF + col0 + tid];
    }

    const __half* Ag = g_h + (size_t)row0 * DIM;
    const __half* Bg = g_h + (size_t)(HALF + col0) * DIM;
    char* tA = dyn;
    char* tB = dyn + 2 * TILEB;

    // cp.async one 128x64 k-block per tile: 1024 x 16B chunks per tile,
    // 2 tiles -> 8 chunks per thread.
    auto prefetch = [&](int kb, int buf) {
        #pragma unroll
        for (int i = 0; i < 8; i++) {
            int id  = tid + i * 256;            // 0..2047
            int idx = id & 1023;
            int r   = idx >> 3, c = idx & 7;    // row, 16B chunk
            const __half* src = ((id >> 10) ? Bg : Ag)
                              + (size_t)r * DIM + kb * KBLK + c * 8;
            unsigned dst = su32((id >> 10) ? tB : tA)
                         + (unsigned)(buf * TILEB + r * ROWB + c * 16);
            asm volatile("cp.async.cg.shared.global [%0], [%1], 16;"
                         :: "r"(dst), "l"(src));
        }
    };

    prefetch(0, 0);
    asm volatile("cp.async.commit_group;" ::: "memory");

    const int m0 = (w >> 2) * 64;
    const int n0 = (w & 3)  * 32;
    const unsigned aoff = (unsigned)((lane & 15) * ROWB + (lane >> 4) * 16);
    const unsigned boff = (unsigned)((lane & 7)  * ROWB + ((lane >> 3) & 1) * 16);

    float acc[4][4][4];
    #pragma unroll
    for (int mt = 0; mt < 4; mt++)
        #pragma unroll
        for (int nt = 0; nt < 4; nt++)
            #pragma unroll
            for (int q = 0; q < 4; q++) acc[mt][nt][q] = 0.0f;

    for (int kb = 0; kb < NKB; kb++) {
        if (kb + 1 < NKB) {
            prefetch(kb + 1, (kb + 1) & 1);
            asm volatile("cp.async.commit_group;" ::: "memory");
            asm volatile("cp.async.wait_group 1;" ::: "memory");
        } else {
            asm volatile("cp.async.wait_group 0;" ::: "memory");
        }
        __syncthreads();

        const unsigned aT = su32(tA) + (kb & 1) * TILEB;
        const unsigned bT = su32(tB) + (kb & 1) * TILEB;
        #pragma unroll
        for (int kk = 0; kk < 4; kk++) {          // four K=16 steps per block
            unsigned a[4][4], b[4][2];
            #pragma unroll
            for (int mt = 0; mt < 4; mt++) {
                unsigned ad = aT + (unsigned)((m0 + mt * 16) * ROWB + kk * 32) + aoff;
                asm volatile(
                    "ldmatrix.sync.aligned.m8n8.x4.shared.b16 {%0,%1,%2,%3}, [%4];"
                    : "=r"(a[mt][0]), "=r"(a[mt][1]), "=r"(a[mt][2]), "=r"(a[mt][3])
                    : "r"(ad));
            }
            #pragma unroll
            for (int nt = 0; nt < 4; nt++) {
                unsigned bd = bT + (unsigned)((n0 + nt * 8) * ROWB + kk * 32) + boff;
                asm volatile(
                    "ldmatrix.sync.aligned.m8n8.x2.shared.b16 {%0,%1}, [%2];"
                    : "=r"(b[nt][0]), "=r"(b[nt][1])
                    : "r"(bd));
            }
            #pragma unroll
            for (int mt = 0; mt < 4; mt++)
                #pragma unroll
                for (int nt = 0; nt < 4; nt++) {
                    asm volatile(
                        "mma.sync.aligned.m16n8k16.row.col.f32.f16.f16.f32 "
                        "{%0,%1,%2,%3}, {%4,%5,%6,%7}, {%8,%9}, {%0,%1,%2,%3};"
                        : "+f"(acc[mt][nt][0]), "+f"(acc[mt][nt][1]),
                          "+f"(acc[mt][nt][2]), "+f"(acc[mt][nt][3])
                        : "r"(a[mt][0]), "r"(a[mt][1]), "r"(a[mt][2]), "r"(a[mt][3]),
                          "r"(b[nt][0]), "r"(b[nt][1]));
                }
        }
        __syncthreads();
    }

    // Epilogue: SQUARED distance + masked hard mining (sqrt commutes with max/min).
    float lrp[8], lrn[8], lcp[8], lcn[8];
    #pragma unroll
    for (int i = 0; i < 8; i++) { lrp[i] = 0.0f; lrn[i] = INFINITY;
                                  lcp[i] = 0.0f; lcn[i] = INFINITY; }

    #pragma unroll
    for (int mt = 0; mt < 4; mt++) {
        #pragma unroll
        for (int h = 0; h < 2; h++) {
            int r = m0 + mt * 16 + h * 8 + (lane >> 2);
            float sr = s_sqr[r];
            int   lr = s_lr[r];
            #pragma unroll
            for (int nt = 0; nt < 4; nt++) {
                #pragma unroll
                for (int q = 0; q < 2; q++) {
                    int c = n0 + nt * 8 + ((lane & 3) << 1) + q;
                    float dot = acc[mt][nt][h * 2 + q];
                    float d2  = fmaxf(fmaf(-2.0f, dot, sr + s_sqc[c]), EPS);
                    int ri = mt * 2 + h, ci = nt * 2 + q;
                    if (lr == s_lc[c]) {
                        lrp[ri] = fmaxf(lrp[ri], d2);
                        lcp[ci] = fmaxf(lcp[ci], d2);
                    } else {
                        lrn[ri] = fminf(lrn[ri], d2);
                        lcn[ci] = fminf(lcn[ci], d2);
                    }
                }
            }
        }
    }

    #pragma unroll
    for (int i = 0; i < 8; i++) {
        int r = m0 + (i >> 1) * 16 + (i & 1) * 8 + (lane >> 2);
        if (lrp[i] > 0.0f)     atomicMax(&s_rp[r], __float_as_uint(lrp[i]));
        if (lrn[i] < INFINITY) atomicMin(&s_rn[r], __float_as_uint(lrn[i]));
    }
    #pragma unroll
    for (int j = 0; j < 8; j++) {
        int c = n0 + (j >> 1) * 8 + ((lane & 3) << 1) + (j & 1);
        if (lcp[j] > 0.0f)     atomicMax(&s_cp[c], __float_as_uint(lcp[j]));
        if (lcn[j] < INFINITY) atomicMin(&s_cn[c], __float_as_uint(lcn[j]));
    }
    __syncthreads();

    if (tid < 128) {
        atomicMax(&g_ap[row0 + tid], s_rp[tid]);
        atomicMin(&g_an[row0 + tid], s_rn[tid]);
    } else {
        int t = tid - 128;
        atomicMax(&g_ap[HALF + col0 + t], s_cp[t]);
        atomicMin(&g_an[HALF + col0 + t], s_cn[t]);
    }

    // ---- Fused final loss: last CTA to finish reduces all anchors. ----
    __threadfence();
    __syncthreads();
    if (tid == 0) s_ticket = atomicAdd(&g_done, 1u);
    __syncthreads();
    if (s_ticket != NCTA - 1) return;

    float sum = 0.0f;
    for (int i = tid; i < N_TOTAL; i += 256) {
        float ap = sqrtf(__uint_as_float(g_ap[i]));
        unsigned anb = g_an[i];
        float an = (anb == 0x7F800000u) ? 1.0f : sqrtf(__uint_as_float(anb));
        sum += fmaxf(ap - an + MARGIN, 0.0f);
    }
    s_red[tid] = sum;
    __syncthreads();
    #pragma unroll
    for (int s = 128; s; s >>= 1) {
        if (tid < s) s_red[tid] += s_red[tid + s];
        __syncthreads();
    }
    if (tid == 0) out[0] = s_red[0] / (float)N_TOTAL;
}

// ---------------------------------------------------------------------------
extern "C" void kernel_launch(void* const* d_in, const int* in_sizes, int n_in,
                              void* d_out, int out_size) {
    const float* inputs  = (const float*)d_in[0];
    const int*   targets = (const int*)d_in[1];
    (void)in_sizes; (void)n_in; (void)out_size;

    const int dyn_bytes = 4 * TILEB;               // 73728 B (2x A + 2x B buffers)
    static bool attr_set = false;
    if (!attr_set) {
        cudaFuncSetAttribute(k_mine, cudaFuncAttributeMaxDynamicSharedMemorySize,
                             dyn_bytes);
        attr_set = true;
    }

    k_normalize<<<N_TOTAL / 8, 256>>>(inputs);
    dim3 grid(HALF / BN, HALF / BM);               // 16 x 16 tiles, single wave @ occ 2
    k_mine<<<grid, 256, dyn_bytes>>>(targets, (float*)d_out);
}

// round 11
// speedup vs baseline: 1.1807x; 1.1807x over previous
#include <cuda_runtime.h>
#include <cuda_fp16.h>
#include <math.h>
#include <cstdint>

#define N_TOTAL 4096
#define HALF    2048
#define DIM     256
#define EPS     1e-6f
#define MARGIN  0.3f

#define BM    128
#define BN    256
#define ROWB  528                    // 512 B data + 16 B pad (4-word bank shift/row)
#define A_BYTES (BM * ROWB)          // 67584
#define B_BYTES (BN * ROWB)          // 135168
#define NCTA  ((HALF / BM) * (HALF / BN))   // 16 * 8 = 128

// Scratch (allocation-free)
__device__ __half   g_h[N_TOTAL * DIM];
__device__ float    g_sq[N_TOTAL];
__device__ unsigned g_ap[N_TOTAL];   // d^2 max over positives (bits), init 0
__device__ unsigned g_an[N_TOTAL];   // d^2 min over negatives (bits), init +inf
__device__ unsigned g_done;          // completion ticket, reset by k_normalize

static __device__ __forceinline__ unsigned su32(const void* p) {
    return (unsigned)__cvta_generic_to_shared(p);
}

// ---------------------------------------------------------------------------
// Kernel 1: L2-normalize rows -> fp16 + fp32 squared norm; reinit buffers.
// One warp per row.
// ---------------------------------------------------------------------------
__global__ void k_normalize(const float* __restrict__ in) {
    int warp = (blockIdx.x * blockDim.x + threadIdx.x) >> 5;
    int lane = threadIdx.x & 31;
    if (warp >= N_TOTAL) return;

    const float4* row = (const float4*)(in + (size_t)warp * DIM);
    float4 v0 = row[lane];
    float4 v1 = row[lane + 32];
    float s = v0.x*v0.x + v0.y*v0.y + v0.z*v0.z + v0.w*v0.w
            + v1.x*v1.x + v1.y*v1.y + v1.z*v1.z + v1.w*v1.w;
    #pragma unroll
    for (int o = 16; o; o >>= 1) s += __shfl_xor_sync(0xffffffffu, s, o);

    float inv = 1.0f / (sqrtf(s) + EPS);

    __half2 h0 = __floats2half2_rn(v0.x * inv, v0.y * inv);
    __half2 h1 = __floats2half2_rn(v0.z * inv, v0.w * inv);
    __half2 h2 = __floats2half2_rn(v1.x * inv, v1.y * inv);
    __half2 h3 = __floats2half2_rn(v1.z * inv, v1.w * inv);

    __half* H = g_h + (size_t)warp * DIM;
    *(__half2*)(H + 4 * lane)           = h0;
    *(__half2*)(H + 4 * lane + 2)       = h1;
    *(__half2*)(H + 128 + 4 * lane)     = h2;
    *(__half2*)(H + 128 + 4 * lane + 2) = h3;

    if (lane == 0) {
        g_sq[warp] = s * inv * inv;
        g_ap[warp] = 0u;
        g_an[warp] = 0x7F800000u;
    }
    if (blockIdx.x == 0 && threadIdx.x == 0) g_done = 0u;
}

// ---------------------------------------------------------------------------
// Kernel 2: single-wave fp16 mma.sync GEMM, full-K panels resident in SMEM
// (one cp.async burst, ONE barrier), fused squared-distance hard mining,
// and (last CTA) the final loss. 512 threads = 16 warps (2x8), warp tile 64x32.
// ---------------------------------------------------------------------------
__global__ void __launch_bounds__(512, 1) k_mine(const int* __restrict__ tgt,
                                                 float* __restrict__ out) {
    extern __shared__ __align__(128) char dyn[];   // A panel then B panel
    __shared__ unsigned s_rp[BM], s_rn[BM], s_cp[BN], s_cn[BN];
    __shared__ int   s_lr[BM], s_lc[BN];
    __shared__ float s_sqr[BM], s_sqc[BN];
    __shared__ float s_red[512];
    __shared__ unsigned s_ticket;

    const int tid  = threadIdx.x, lane = tid & 31, w = tid >> 5;
    const int row0 = blockIdx.y * BM;          // 16 row blocks
    const int col0 = blockIdx.x * BN;          // 8  col blocks

    if (tid < 128) {
        s_rp[tid] = 0u;  s_rn[tid] = 0x7F800000u;
        s_lr[tid]  = tgt[row0 + tid];
        s_sqr[tid] = g_sq[row0 + tid];
    }
    if (tid < 256) {
        s_cp[tid] = 0u;  s_cn[tid] = 0x7F800000u;
        s_lc[tid]  = tgt[HALF + col0 + tid];
        s_sqc[tid] = g_sq[HALF + col0 + tid];
    }

    // One burst: A = 128 rows x 32 chunks, B = 256 rows x 32 chunks (16B chunks)
    const __half* Ag = g_h + (size_t)row0 * DIM;
    const __half* Bg = g_h + (size_t)(HALF + col0) * DIM;
    char* tA = dyn;
    char* tB = dyn + A_BYTES;
    #pragma unroll
    for (int i = 0; i < 24; i++) {
        int id = tid + i * 512;                // 0..12287
        if (id < 4096) {
            int r = id >> 5, c = id & 31;
            asm volatile("cp.async.cg.shared.global [%0], [%1], 16;"
                :: "r"(su32(tA) + (unsigned)(r * ROWB + c * 16)),
                   "l"(Ag + (size_t)r * DIM + c * 8));
        } else {
            int b = id - 4096;
            int r = b >> 5, c = b & 31;
            asm volatile("cp.async.cg.shared.global [%0], [%1], 16;"
                :: "r"(su32(tB) + (unsigned)(r * ROWB + c * 16)),
                   "l"(Bg + (size_t)r * DIM + c * 8));
        }
    }
    asm volatile("cp.async.commit_group;" ::: "memory");

    const int m0 = (w >> 3) * 64;              // {0, 64}
    const int n0 = (w & 7)  * 32;              // 0..224
    const unsigned aoff = (unsigned)((lane & 15) * ROWB + (lane >> 4) * 16);
    const unsigned boff = (unsigned)((lane & 7)  * ROWB + ((lane >> 3) & 1) * 16);
    const unsigned aT = su32(tA);
    const unsigned bT = su32(tB);

    float acc[4][4][4];
    #pragma unroll
    for (int mt = 0; mt < 4; mt++)
        #pragma unroll
        for (int nt = 0; nt < 4; nt++)
            #pragma unroll
            for (int q = 0; q < 4; q++) acc[mt][nt][q] = 0.0f;

    asm volatile("cp.async.wait_group 0;" ::: "memory");
    __syncthreads();                           // the ONLY mainloop barrier

    #pragma unroll
    for (int kk = 0; kk < DIM / 16; kk++) {    // 16 K-steps, no further syncs
        unsigned a[4][4], b[4][2];
        #pragma unroll
        for (int mt = 0; mt < 4; mt++) {
            unsigned ad = aT + (unsigned)((m0 + mt * 16) * ROWB + kk * 32) + aoff;
            asm volatile(
                "ldmatrix.sync.aligned.m8n8.x4.shared.b16 {%0,%1,%2,%3}, [%4];"
                : "=r"(a[mt][0]), "=r"(a[mt][1]), "=r"(a[mt][2]), "=r"(a[mt][3])
                : "r"(ad));
        }
        #pragma unroll
        for (int nt = 0; nt < 4; nt++) {
            unsigned bd = bT + (unsigned)((n0 + nt * 8) * ROWB + kk * 32) + boff;
            asm volatile(
                "ldmatrix.sync.aligned.m8n8.x2.shared.b16 {%0,%1}, [%2];"
                : "=r"(b[nt][0]), "=r"(b[nt][1])
                : "r"(bd));
        }
        #pragma unroll
        for (int mt = 0; mt < 4; mt++)
            #pragma unroll
            for (int nt = 0; nt < 4; nt++) {
                asm volatile(
                    "mma.sync.aligned.m16n8k16.row.col.f32.f16.f16.f32 "
                    "{%0,%1,%2,%3}, {%4,%5,%6,%7}, {%8,%9}, {%0,%1,%2,%3};"
                    : "+f"(acc[mt][nt][0]), "+f"(acc[mt][nt][1]),
                      "+f"(acc[mt][nt][2]), "+f"(acc[mt][nt][3])
                    : "r"(a[mt][0]), "r"(a[mt][1]), "r"(a[mt][2]), "r"(a[mt][3]),
                      "r"(b[nt][0]), "r"(b[nt][1]));
            }
    }

    // Epilogue: SQUARED distance + masked hard mining (sqrt deferred).
    float lrp[8], lrn[8], lcp[8], lcn[8];
    #pragma unroll
    for (int i = 0; i < 8; i++) { lrp[i] = 0.0f; lrn[i] = INFINITY;
                                  lcp[i] = 0.0f; lcn[i] = INFINITY; }

    #pragma unroll
    for (int mt = 0; mt < 4; mt++) {
        #pragma unroll
        for (int h = 0; h < 2; h++) {
            int r = m0 + mt * 16 + h * 8 + (lane >> 2);
            float sr = s_sqr[r];
            int   lr = s_lr[r];
            #pragma unroll
            for (int nt = 0; nt < 4; nt++) {
                #pragma unroll
                for (int q = 0; q < 2; q++) {
                    int c = n0 + nt * 8 + ((lane & 3) << 1) + q;
                    float dot = acc[mt][nt][h * 2 + q];
                    float d2  = fmaxf(fmaf(-2.0f, dot, sr + s_sqc[c]), EPS);
                    int ri = mt * 2 + h, ci = nt * 2 + q;
                    if (lr == s_lc[c]) {
                        lrp[ri] = fmaxf(lrp[ri], d2);
                        lcp[ci] = fmaxf(lcp[ci], d2);
                    } else {
                        lrn[ri] = fminf(lrn[ri], d2);
                        lcn[ci] = fminf(lcn[ci], d2);
                    }
                }
            }
        }
    }

    #pragma unroll
    for (int i = 0; i < 8; i++) {
        int r = m0 + (i >> 1) * 16 + (i & 1) * 8 + (lane >> 2);
        if (lrp[i] > 0.0f)     atomicMax(&s_rp[r], __float_as_uint(lrp[i]));
        if (lrn[i] < INFINITY) atomicMin(&s_rn[r], __float_as_uint(lrn[i]));
    }
    #pragma unroll
    for (int j = 0; j < 8; j++) {
        int c = n0 + (j >> 1) * 8 + ((lane & 3) << 1) + (j & 1);
        if (lcp[j] > 0.0f)     atomicMax(&s_cp[c], __float_as_uint(lcp[j]));
        if (lcn[j] < INFINITY) atomicMin(&s_cn[c], __float_as_uint(lcn[j]));
    }
    __syncthreads();

    if (tid < 128) {
        atomicMax(&g_ap[row0 + tid], s_rp[tid]);
        atomicMin(&g_an[row0 + tid], s_rn[tid]);
    } else if (tid < 384) {
        int t = tid - 128;
        atomicMax(&g_ap[HALF + col0 + t], s_cp[t]);
        atomicMin(&g_an[HALF + col0 + t], s_cn[t]);
    }

    // ---- Fused final loss: last CTA to finish reduces all anchors. ----
    __threadfence();
    __syncthreads();
    if (tid == 0) s_ticket = atomicAdd(&g_done, 1u);
    __syncthreads();
    if (s_ticket != NCTA - 1) return;

    float sum = 0.0f;
    for (int i = tid; i < N_TOTAL; i += 512) {
        float ap = sqrtf(__uint_as_float(g_ap[i]));
        unsigned anb = g_an[i];
        float an = (anb == 0x7F800000u) ? 1.0f : sqrtf(__uint_as_float(anb));
        sum += fmaxf(ap - an + MARGIN, 0.0f);
    }
    s_red[tid] = sum;
    __syncthreads();
    #pragma unroll
    for (int s = 256; s; s >>= 1) {
        if (tid < s) s_red[tid] += s_red[tid + s];
        __syncthreads();
    }
    if (tid == 0) out[0] = s_red[0] / (float)N_TOTAL;
}

// ---------------------------------------------------------------------------
extern "C" void kernel_launch(void* const* d_in, const int* in_sizes, int n_in,
                              void* d_out, int out_size) {
    const float* inputs  = (const float*)d_in[0];
    const int*   targets = (const int*)d_in[1];
    (void)in_sizes; (void)n_in; (void)out_size;

    const int dyn_bytes = A_BYTES + B_BYTES;       // 202752 B
    static bool attr_set = false;
    if (!attr_set) {
        cudaFuncSetAttribute(k_mine, cudaFuncAttributeMaxDynamicSharedMemorySize,
                             dyn_bytes);
        attr_set = true;
    }

    k_normalize<<<N_TOTAL / 8, 256>>>(inputs);
    dim3 grid(HALF / BN, HALF / BM);               // 8 x 16 = 128 CTAs, single wave
    k_mine<<<grid, 512, dyn_bytes>>>(targets, (float*)d_out);
}